// round 3
// baseline (speedup 1.0000x reference)
#include <cuda_runtime.h>
#include <math.h>

// Problem shape (fixed by the reference setup_inputs)
#define BATCH 8
#define CHAN  256
#define HH    512
#define WW    512
#define POOLK 16
#define PHROWS 32                      // 512/16 pooled rows
#define SLABS (BATCH * CHAN * PHROWS)  // 65536 CTAs in pass 1
#define NPC   8192.0                   // pooled samples per channel = B*32*32

// Scratch (device globals — no allocation). Every slot is rewritten each
// launch, so no zero-init pass is needed and replays are deterministic.
__device__ float g_part[(size_t)SLABS * 5];  // per-slab moments: S1,S2,S11,S22,S12
__device__ float g_corr[CHAN];               // per-channel |corr|

// ---------------------------------------------------------------------------
// Pass 1: one CTA handles one (b, c, pooled_row) slab: 16 rows x 512 cols of
// each feature. Produces the 5 moment partial-sums over that slab's 32 pooled
// values. Fully coalesced float4 streaming; deterministic shuffle reductions.
// ---------------------------------------------------------------------------
__global__ __launch_bounds__(256)
void fal_moments_kernel(const float* __restrict__ f1,
                        const float* __restrict__ f2) {
    const int ph = blockIdx.x;   // 0..31 pooled row
    const int c  = blockIdx.y;   // 0..255 channel
    const int b  = blockIdx.z;   // 0..7 batch
    const int tid = threadIdx.x;

    // Base of this slab in elements
    const size_t base = ((size_t)(b * CHAN + c) * HH + (size_t)ph * POOLK) * WW;

    // Each thread owns one float4 column (col4 = tid & 127) and rows
    // {r0, r0+2, r0+4, ...} with r0 = tid>>7 in {0,1}. Its pooled-column is
    // fixed: pc = col4 / 4. 8 iterations cover all 16 rows.
    const int col4 = tid & 127;
    const int r0   = tid >> 7;

    const float4* __restrict__ p1 =
        reinterpret_cast<const float4*>(f1 + base) + (size_t)r0 * 128 + col4;
    const float4* __restrict__ p2 =
        reinterpret_cast<const float4*>(f2 + base) + (size_t)r0 * 128 + col4;

    float a1 = 0.0f, a2 = 0.0f;
#pragma unroll
    for (int i = 0; i < 8; i++) {
        float4 v = __ldg(p1 + (size_t)i * 256);   // +2 rows = 256 float4
        float4 w = __ldg(p2 + (size_t)i * 256);
        a1 += (v.x + v.y) + (v.z + v.w);
        a2 += (w.x + w.y) + (w.z + w.w);
    }

    // Fold 256 thread-partials -> 32 pooled sums per feature.
    __shared__ float s1[256];
    __shared__ float s2[256];
    s1[tid] = a1;
    s2[tid] = a2;
    __syncthreads();
    if (tid < 128) {
        s1[tid] += s1[tid + 128];
        s2[tid] += s2[tid + 128];
    }
    __syncthreads();

    if (tid < 32) {
        const int j = tid * 4;
        float pv1 = ((s1[j] + s1[j + 1]) + (s1[j + 2] + s1[j + 3])) * (1.0f / 256.0f);
        float pv2 = ((s2[j] + s2[j + 1]) + (s2[j + 2] + s2[j + 3])) * (1.0f / 256.0f);

        float m1  = pv1;
        float m2  = pv2;
        float m11 = pv1 * pv1;
        float m22 = pv2 * pv2;
        float m12 = pv1 * pv2;

#pragma unroll
        for (int off = 16; off > 0; off >>= 1) {
            m1  += __shfl_down_sync(0xffffffffu, m1,  off);
            m2  += __shfl_down_sync(0xffffffffu, m2,  off);
            m11 += __shfl_down_sync(0xffffffffu, m11, off);
            m22 += __shfl_down_sync(0xffffffffu, m22, off);
            m12 += __shfl_down_sync(0xffffffffu, m12, off);
        }

        if (tid == 0) {
            const size_t slab = ((size_t)(b * CHAN + c) * PHROWS + ph) * 5;
            g_part[slab + 0] = m1;
            g_part[slab + 1] = m2;
            g_part[slab + 2] = m11;
            g_part[slab + 3] = m22;
            g_part[slab + 4] = m12;
        }
    }
}

// ---------------------------------------------------------------------------
// Pass 2: one block per channel. Gather the channel's 256 slab partials,
// reduce in double, compute |corr| exactly as the reference does
// (biased covariance, unbiased std, +1e-8 in denominator).
// ---------------------------------------------------------------------------
__global__ __launch_bounds__(256)
void fal_corr_kernel() {
    const int c = blockIdx.x;
    const int t = threadIdx.x;          // = b*32 + ph
    const int b = t >> 5;
    const int ph = t & 31;
    const size_t slab = ((size_t)(b * CHAN + c) * PHROWS + ph) * 5;

    double m1  = (double)g_part[slab + 0];
    double m2  = (double)g_part[slab + 1];
    double m11 = (double)g_part[slab + 2];
    double m22 = (double)g_part[slab + 3];
    double m12 = (double)g_part[slab + 4];

#pragma unroll
    for (int off = 16; off > 0; off >>= 1) {
        m1  += __shfl_down_sync(0xffffffffu, m1,  off);
        m2  += __shfl_down_sync(0xffffffffu, m2,  off);
        m11 += __shfl_down_sync(0xffffffffu, m11, off);
        m22 += __shfl_down_sync(0xffffffffu, m22, off);
        m12 += __shfl_down_sync(0xffffffffu, m12, off);
    }

    __shared__ double sh[5][8];
    const int lane = t & 31;
    const int w = t >> 5;
    if (lane == 0) {
        sh[0][w] = m1; sh[1][w] = m2; sh[2][w] = m11;
        sh[3][w] = m22; sh[4][w] = m12;
    }
    __syncthreads();

    if (t == 0) {
        double S1 = 0.0, S2 = 0.0, S11 = 0.0, S22 = 0.0, S12 = 0.0;
#pragma unroll
        for (int i = 0; i < 8; i++) {
            S1 += sh[0][i]; S2 += sh[1][i]; S11 += sh[2][i];
            S22 += sh[3][i]; S12 += sh[4][i];
        }
        const double n = NPC;
        const double mean1 = S1 / n;
        const double mean2 = S2 / n;
        const double cov = S12 / n - mean1 * mean2;       // biased (torch.mean)
        const double ss1 = S11 - S1 * S1 / n;
        const double ss2 = S22 - S2 * S2 / n;
        const double std1 = sqrt(ss1 / (n - 1.0));        // unbiased (torch.std)
        const double std2 = sqrt(ss2 / (n - 1.0));
        const double corr = cov / (std1 * std2 + 1e-8);
        g_corr[c] = (float)fabs(corr);
    }
}

// ---------------------------------------------------------------------------
// Pass 3: reduce 256 |corr| -> out[0] = 1 - mean(|corr|)
// ---------------------------------------------------------------------------
__global__ __launch_bounds__(256)
void fal_final_kernel(float* __restrict__ out) {
    const int t = threadIdx.x;
    float v = g_corr[t];
#pragma unroll
    for (int off = 16; off > 0; off >>= 1)
        v += __shfl_down_sync(0xffffffffu, v, off);

    __shared__ float sh[8];
    const int lane = t & 31;
    const int w = t >> 5;
    if (lane == 0) sh[w] = v;
    __syncthreads();

    if (t == 0) {
        float s = 0.0f;
#pragma unroll
        for (int i = 0; i < 8; i++) s += sh[i];
        out[0] = 1.0f - s * (1.0f / 256.0f);
    }
}

extern "C" void kernel_launch(void* const* d_in, const int* in_sizes, int n_in,
                              void* d_out, int out_size) {
    const float* f1 = (const float*)d_in[0];
    const float* f2 = (const float*)d_in[1];
    float* out = (float*)d_out;

    dim3 grid(PHROWS, CHAN, BATCH);   // 32 x 256 x 8 = 65536 CTAs
    fal_moments_kernel<<<grid, 256>>>(f1, f2);
    fal_corr_kernel<<<CHAN, 256>>>();
    fal_final_kernel<<<1, 256>>>(out);
}

// round 4
// speedup vs baseline: 1.0027x; 1.0027x over previous
#include <cuda_runtime.h>
#include <math.h>

// Problem shape (fixed by the reference setup_inputs)
#define BATCH 8
#define CHAN  256
#define HH    512
#define WW    512
#define POOLK 16
#define PHROWS 32                      // 512/16 pooled rows
#define SLABS (BATCH * CHAN * PHROWS)  // 65536 CTAs in pass 1
#define NPC   8192.0                   // pooled samples per channel = B*32*32

// Scratch (device globals — no allocation). g_part/g_corr slots are fully
// rewritten each launch; g_ticket is zero at load and reset to zero by the
// finalizing block each launch -> deterministic across graph replays.
__device__ float g_part[(size_t)SLABS * 5];  // per-slab moments: S1,S2,S11,S22,S12
__device__ float g_corr[CHAN];               // per-channel |corr|
__device__ unsigned int g_ticket;            // last-block-finalize counter

// ---------------------------------------------------------------------------
// Pass 1: one CTA per (b, c, pooled_row) slab: 16 rows x 512 cols of each
// feature. Streaming (evict-first) float4 loads, fully coalesced. Produces the
// 5 moment partial-sums over the slab's 32 pooled values. Deterministic.
// ---------------------------------------------------------------------------
__global__ __launch_bounds__(256)
void fal_moments_kernel(const float* __restrict__ f1,
                        const float* __restrict__ f2) {
    const int ph = blockIdx.x;   // 0..31 pooled row
    const int c  = blockIdx.y;   // 0..255 channel
    const int b  = blockIdx.z;   // 0..7 batch
    const int tid = threadIdx.x;

    const size_t base = ((size_t)(b * CHAN + c) * HH + (size_t)ph * POOLK) * WW;

    // Thread owns one float4 column (col4 = tid & 127), rows {r0, r0+2, ...}
    // with r0 = tid>>7. 8 iterations cover all 16 rows of the slab.
    const int col4 = tid & 127;
    const int r0   = tid >> 7;

    const float4* __restrict__ p1 =
        reinterpret_cast<const float4*>(f1 + base) + (size_t)r0 * 128 + col4;
    const float4* __restrict__ p2 =
        reinterpret_cast<const float4*>(f2 + base) + (size_t)r0 * 128 + col4;

    float a1 = 0.0f, a2 = 0.0f;
#pragma unroll
    for (int i = 0; i < 8; i++) {
        float4 v = __ldcs(p1 + (size_t)i * 256);   // +2 rows = 256 float4
        float4 w = __ldcs(p2 + (size_t)i * 256);
        a1 += (v.x + v.y) + (v.z + v.w);
        a2 += (w.x + w.y) + (w.z + w.w);
    }

    // Fold 256 thread-partials -> 32 pooled sums per feature.
    __shared__ float s1[256];
    __shared__ float s2[256];
    s1[tid] = a1;
    s2[tid] = a2;
    __syncthreads();
    if (tid < 128) {
        s1[tid] += s1[tid + 128];
        s2[tid] += s2[tid + 128];
    }
    __syncthreads();

    if (tid < 32) {
        const int j = tid * 4;
        float pv1 = ((s1[j] + s1[j + 1]) + (s1[j + 2] + s1[j + 3])) * (1.0f / 256.0f);
        float pv2 = ((s2[j] + s2[j + 1]) + (s2[j + 2] + s2[j + 3])) * (1.0f / 256.0f);

        float m1  = pv1;
        float m2  = pv2;
        float m11 = pv1 * pv1;
        float m22 = pv2 * pv2;
        float m12 = pv1 * pv2;

#pragma unroll
        for (int off = 16; off > 0; off >>= 1) {
            m1  += __shfl_down_sync(0xffffffffu, m1,  off);
            m2  += __shfl_down_sync(0xffffffffu, m2,  off);
            m11 += __shfl_down_sync(0xffffffffu, m11, off);
            m22 += __shfl_down_sync(0xffffffffu, m22, off);
            m12 += __shfl_down_sync(0xffffffffu, m12, off);
        }

        if (tid == 0) {
            const size_t slab = ((size_t)(b * CHAN + c) * PHROWS + ph) * 5;
            g_part[slab + 0] = m1;
            g_part[slab + 1] = m2;
            g_part[slab + 2] = m11;
            g_part[slab + 3] = m22;
            g_part[slab + 4] = m12;
        }
    }
}

// ---------------------------------------------------------------------------
// Pass 2 (fused with final): one block per channel gathers its 256 slab
// partials, reduces in double (matches reference: biased cov, unbiased std,
// +1e-8), writes |corr|. The last block to finish reduces all 256 |corr|
// values and writes out[0] = 1 - mean, then resets the ticket.
// ---------------------------------------------------------------------------
__global__ __launch_bounds__(256)
void fal_corr_final_kernel(float* __restrict__ out) {
    const int c = blockIdx.x;
    const int t = threadIdx.x;          // = b*32 + ph
    const int b = t >> 5;
    const int ph = t & 31;
    const size_t slab = ((size_t)(b * CHAN + c) * PHROWS + ph) * 5;

    double m1  = (double)g_part[slab + 0];
    double m2  = (double)g_part[slab + 1];
    double m11 = (double)g_part[slab + 2];
    double m22 = (double)g_part[slab + 3];
    double m12 = (double)g_part[slab + 4];

#pragma unroll
    for (int off = 16; off > 0; off >>= 1) {
        m1  += __shfl_down_sync(0xffffffffu, m1,  off);
        m2  += __shfl_down_sync(0xffffffffu, m2,  off);
        m11 += __shfl_down_sync(0xffffffffu, m11, off);
        m22 += __shfl_down_sync(0xffffffffu, m22, off);
        m12 += __shfl_down_sync(0xffffffffu, m12, off);
    }

    __shared__ double sh[5][8];
    const int lane = t & 31;
    const int w = t >> 5;
    if (lane == 0) {
        sh[0][w] = m1; sh[1][w] = m2; sh[2][w] = m11;
        sh[3][w] = m22; sh[4][w] = m12;
    }
    __syncthreads();

    if (t == 0) {
        double S1 = 0.0, S2 = 0.0, S11 = 0.0, S22 = 0.0, S12 = 0.0;
#pragma unroll
        for (int i = 0; i < 8; i++) {
            S1 += sh[0][i]; S2 += sh[1][i]; S11 += sh[2][i];
            S22 += sh[3][i]; S12 += sh[4][i];
        }
        const double n = NPC;
        const double mean1 = S1 / n;
        const double mean2 = S2 / n;
        const double cov = S12 / n - mean1 * mean2;       // biased (torch.mean)
        const double ss1 = S11 - S1 * S1 / n;
        const double ss2 = S22 - S2 * S2 / n;
        const double std1 = sqrt(ss1 / (n - 1.0));        // unbiased (torch.std)
        const double std2 = sqrt(ss2 / (n - 1.0));
        const double corr = cov / (std1 * std2 + 1e-8);
        g_corr[c] = (float)fabs(corr);
    }

    // ---- last-block finalize ----
    __shared__ bool is_last;
    __threadfence();                       // publish g_corr[c]
    if (t == 0) {
        unsigned int old = atomicAdd(&g_ticket, 1u);
        is_last = (old == CHAN - 1);
    }
    __syncthreads();
    if (!is_last) return;
    __threadfence();                       // acquire all g_corr writes

    float v = g_corr[t];
#pragma unroll
    for (int off = 16; off > 0; off >>= 1)
        v += __shfl_down_sync(0xffffffffu, v, off);

    __shared__ float shf[8];
    if (lane == 0) shf[w] = v;
    __syncthreads();

    if (t == 0) {
        float s = 0.0f;
#pragma unroll
        for (int i = 0; i < 8; i++) s += shf[i];
        out[0] = 1.0f - s * (1.0f / 256.0f);
        g_ticket = 0u;                     // reset for next graph replay
    }
}

extern "C" void kernel_launch(void* const* d_in, const int* in_sizes, int n_in,
                              void* d_out, int out_size) {
    const float* f1 = (const float*)d_in[0];
    const float* f2 = (const float*)d_in[1];
    float* out = (float*)d_out;

    dim3 grid(PHROWS, CHAN, BATCH);   // 32 x 256 x 8 = 65536 CTAs
    fal_moments_kernel<<<grid, 256>>>(f1, f2);
    fal_corr_final_kernel<<<CHAN, 256>>>(out);
}

// round 6
// speedup vs baseline: 1.0143x; 1.0115x over previous
#include <cuda_runtime.h>
#include <math.h>

// Problem shape (fixed by the reference setup_inputs)
#define BATCH 8
#define CHAN  256
#define HH    512
#define WW    512
#define POOLK 16
#define PHROWS 32                      // 512/16 pooled rows
#define SLABS (BATCH * CHAN * PHROWS)  // 65536 CTAs
#define SLABS_PER_CHAN (BATCH * PHROWS)  // 256
#define NPC   8192.0                   // pooled samples per channel = B*32*32

// Scratch (device globals — no allocation). All data slots are fully
// rewritten each launch; all tickets start at 0 (module load) and are reset
// to 0 by their finalizer each launch -> deterministic across graph replays.
__device__ float g_part[(size_t)SLABS * 5];   // per-slab moments S1,S2,S11,S22,S12
__device__ float g_corr[CHAN];                // per-channel |corr|
__device__ unsigned int g_chan_ticket[CHAN];  // per-channel arrival counters
__device__ unsigned int g_ticket;             // global finalize counter

// ---------------------------------------------------------------------------
// Single fused kernel.
// Phase A (every CTA): stream one (b, c, pooled_row) slab = 16x512 of each
//   feature, fully coalesced evict-first float4 loads; produce the 5 moment
//   partials over the slab's 32 pooled values; write to g_part.
// Phase B (last CTA per channel): reduce the channel's 256 slab partials in
//   double (biased cov, unbiased std, +1e-8 — exactly the reference) -> g_corr.
// Phase C (last channel finalizer): out[0] = 1 - mean(|corr|).
// Reduction orders are fixed -> bitwise deterministic.
// ---------------------------------------------------------------------------
__global__ __launch_bounds__(256)
void fal_fused_kernel(const float* __restrict__ f1,
                      const float* __restrict__ f2,
                      float* __restrict__ out) {
    const int ph = blockIdx.x;   // 0..31 pooled row
    const int c  = blockIdx.y;   // 0..255 channel
    const int b  = blockIdx.z;   // 0..7 batch
    const int tid = threadIdx.x;
    const int lane = tid & 31;
    const int w = tid >> 5;

    // ---------------- Phase A: slab streaming + moments ----------------
    const size_t base = ((size_t)(b * CHAN + c) * HH + (size_t)ph * POOLK) * WW;

    const int col4 = tid & 127;
    const int r0   = tid >> 7;

    const float4* __restrict__ p1 =
        reinterpret_cast<const float4*>(f1 + base) + (size_t)r0 * 128 + col4;
    const float4* __restrict__ p2 =
        reinterpret_cast<const float4*>(f2 + base) + (size_t)r0 * 128 + col4;

    float a1 = 0.0f, a2 = 0.0f;
#pragma unroll
    for (int i = 0; i < 8; i++) {
        float4 v = __ldcs(p1 + (size_t)i * 256);   // +2 rows = 256 float4
        float4 w4 = __ldcs(p2 + (size_t)i * 256);
        a1 += (v.x + v.y) + (v.z + v.w);
        a2 += (w4.x + w4.y) + (w4.z + w4.w);
    }

    __shared__ float s1[256];
    __shared__ float s2[256];
    s1[tid] = a1;
    s2[tid] = a2;
    __syncthreads();
    if (tid < 128) {
        s1[tid] += s1[tid + 128];
        s2[tid] += s2[tid + 128];
    }
    __syncthreads();

    if (tid < 32) {
        const int j = tid * 4;
        float pv1 = ((s1[j] + s1[j + 1]) + (s1[j + 2] + s1[j + 3])) * (1.0f / 256.0f);
        float pv2 = ((s2[j] + s2[j + 1]) + (s2[j + 2] + s2[j + 3])) * (1.0f / 256.0f);

        float m1  = pv1;
        float m2  = pv2;
        float m11 = pv1 * pv1;
        float m22 = pv2 * pv2;
        float m12 = pv1 * pv2;

#pragma unroll
        for (int off = 16; off > 0; off >>= 1) {
            m1  += __shfl_down_sync(0xffffffffu, m1,  off);
            m2  += __shfl_down_sync(0xffffffffu, m2,  off);
            m11 += __shfl_down_sync(0xffffffffu, m11, off);
            m22 += __shfl_down_sync(0xffffffffu, m22, off);
            m12 += __shfl_down_sync(0xffffffffu, m12, off);
        }

        if (tid == 0) {
            const size_t slab = ((size_t)(b * CHAN + c) * PHROWS + ph) * 5;
            g_part[slab + 0] = m1;
            g_part[slab + 1] = m2;
            g_part[slab + 2] = m11;
            g_part[slab + 3] = m22;
            g_part[slab + 4] = m12;
        }
    }

    // ---------------- Phase B: last CTA of this channel finalizes ----------
    __shared__ bool chan_last;
    __threadfence();                       // publish this CTA's g_part slot
    if (tid == 0) {
        unsigned int old = atomicAdd(&g_chan_ticket[c], 1u);
        chan_last = (old == SLABS_PER_CHAN - 1);
    }
    __syncthreads();
    if (!chan_last) return;
    __threadfence();                       // acquire all slabs of channel c

    {
        // t = b*32 + ph indexes the channel's 256 slabs
        const int tb = tid >> 5;           // batch  (0..7)
        const int tp = tid & 31;           // pooled row (0..31)
        const size_t slab = ((size_t)(tb * CHAN + c) * PHROWS + tp) * 5;

        double m1  = (double)g_part[slab + 0];
        double m2  = (double)g_part[slab + 1];
        double m11 = (double)g_part[slab + 2];
        double m22 = (double)g_part[slab + 3];
        double m12 = (double)g_part[slab + 4];

#pragma unroll
        for (int off = 16; off > 0; off >>= 1) {
            m1  += __shfl_down_sync(0xffffffffu, m1,  off);
            m2  += __shfl_down_sync(0xffffffffu, m2,  off);
            m11 += __shfl_down_sync(0xffffffffu, m11, off);
            m22 += __shfl_down_sync(0xffffffffu, m22, off);
            m12 += __shfl_down_sync(0xffffffffu, m12, off);
        }

        __shared__ double sh[5][8];
        if (lane == 0) {
            sh[0][w] = m1; sh[1][w] = m2; sh[2][w] = m11;
            sh[3][w] = m22; sh[4][w] = m12;
        }
        __syncthreads();

        if (tid == 0) {
            double S1 = 0.0, S2 = 0.0, S11 = 0.0, S22 = 0.0, S12 = 0.0;
#pragma unroll
            for (int i = 0; i < 8; i++) {
                S1 += sh[0][i]; S2 += sh[1][i]; S11 += sh[2][i];
                S22 += sh[3][i]; S12 += sh[4][i];
            }
            const double n = NPC;
            const double mean1 = S1 / n;
            const double mean2 = S2 / n;
            const double cov = S12 / n - mean1 * mean2;   // biased (torch.mean)
            const double ss1 = S11 - S1 * S1 / n;
            const double ss2 = S22 - S2 * S2 / n;
            const double std1 = sqrt(ss1 / (n - 1.0));    // unbiased (torch.std)
            const double std2 = sqrt(ss2 / (n - 1.0));
            const double corr = cov / (std1 * std2 + 1e-8);
            g_corr[c] = (float)fabs(corr);
            g_chan_ticket[c] = 0u;         // reset for next graph replay
        }
    }

    // ---------------- Phase C: last channel finalizer reduces g_corr -------
    __shared__ bool all_last;
    __threadfence();                       // publish g_corr[c]
    if (tid == 0) {
        unsigned int old = atomicAdd(&g_ticket, 1u);
        all_last = (old == CHAN - 1);
    }
    __syncthreads();
    if (!all_last) return;
    __threadfence();                       // acquire all g_corr writes

    {
        float v = g_corr[tid];
#pragma unroll
        for (int off = 16; off > 0; off >>= 1)
            v += __shfl_down_sync(0xffffffffu, v, off);

        __shared__ float shf[8];
        if (lane == 0) shf[w] = v;
        __syncthreads();

        if (tid == 0) {
            float s = 0.0f;
#pragma unroll
            for (int i = 0; i < 8; i++) s += shf[i];
            out[0] = 1.0f - s * (1.0f / 256.0f);
            g_ticket = 0u;                 // reset for next graph replay
        }
    }
}

extern "C" void kernel_launch(void* const* d_in, const int* in_sizes, int n_in,
                              void* d_out, int out_size) {
    const float* f1 = (const float*)d_in[0];
    const float* f2 = (const float*)d_in[1];
    float* out = (float*)d_out;

    dim3 grid(PHROWS, CHAN, BATCH);   // 32 x 256 x 8 = 65536 CTAs
    fal_fused_kernel<<<grid, 256>>>(f1, f2, out);
}

// round 8
// speedup vs baseline: 1.0201x; 1.0057x over previous
#include <cuda_runtime.h>
#include <math.h>

// Problem shape (fixed by the reference setup_inputs)
#define BATCH 8
#define CHAN  256
#define HH    512
#define WW    512
#define POOLK 16
#define PHROWS 32                        // 512/16 pooled rows
#define SLABS (BATCH * CHAN * PHROWS)    // 65536 CTAs
#define CBPAIRS (BATCH * CHAN)           // 2048 (channel,batch) groups
#define NPC   8192.0                     // pooled samples per channel = B*32*32

// Scratch (device globals — no allocation). All data slots are fully
// rewritten each launch; all tickets start at 0 (module load) and are reset
// to 0 by their finalizer each launch -> deterministic across graph replays.
__device__ float  g_part[(size_t)SLABS * 5];    // per-slab moments S1,S2,S11,S22,S12
__device__ double g_part2[(size_t)CBPAIRS * 5]; // per-(c,b) moments (double)
__device__ float  g_corr[CHAN];                 // per-channel |corr|
__device__ unsigned int g_cb_ticket[CBPAIRS];   // level-1 arrival counters (32 each)
__device__ unsigned int g_chan_ticket[CHAN];    // level-2 arrival counters (8 each)
__device__ unsigned int g_ticket;               // level-3 counter (256)

// ---------------------------------------------------------------------------
// Single fused kernel, hierarchical finalize.
// Phase A  (every CTA): stream one (b, c, pooled_row) slab = 16x512 of each
//   feature (coalesced evict-first float4); 5 moment partials -> g_part.
// Phase B1 (last CTA of each (c,b) group, warp 0): reduce 32 slabs -> g_part2.
// Phase B2 (last group of each channel, warp 0): reduce 8 batches, compute
//   |corr| exactly as the reference (biased cov, unbiased std, +1e-8).
// Phase C  (last channel): out[0] = 1 - mean(|corr|).
// All reduction orders fixed -> bitwise deterministic across replays.
// ---------------------------------------------------------------------------
__global__ __launch_bounds__(256)
void fal_fused_kernel(const float* __restrict__ f1,
                      const float* __restrict__ f2,
                      float* __restrict__ out) {
    const int ph = blockIdx.x;   // 0..31 pooled row
    const int c  = blockIdx.y;   // 0..255 channel
    const int b  = blockIdx.z;   // 0..7 batch
    const int tid = threadIdx.x;
    const int lane = tid & 31;
    const int w = tid >> 5;
    const int cb = b * CHAN + c;

    // ---------------- Phase A: slab streaming + moments ----------------
    const size_t base = ((size_t)cb * HH + (size_t)ph * POOLK) * WW;

    const int col4 = tid & 127;
    const int r0   = tid >> 7;

    const float4* __restrict__ p1 =
        reinterpret_cast<const float4*>(f1 + base) + (size_t)r0 * 128 + col4;
    const float4* __restrict__ p2 =
        reinterpret_cast<const float4*>(f2 + base) + (size_t)r0 * 128 + col4;

    float a1 = 0.0f, a2 = 0.0f;
#pragma unroll
    for (int i = 0; i < 8; i++) {
        float4 v  = __ldcs(p1 + (size_t)i * 256);   // +2 rows = 256 float4
        float4 w4 = __ldcs(p2 + (size_t)i * 256);
        a1 += (v.x + v.y) + (v.z + v.w);
        a2 += (w4.x + w4.y) + (w4.z + w4.w);
    }

    __shared__ float s1[256];
    __shared__ float s2[256];
    s1[tid] = a1;
    s2[tid] = a2;
    __syncthreads();
    if (tid < 128) {
        s1[tid] += s1[tid + 128];
        s2[tid] += s2[tid + 128];
    }
    __syncthreads();

    if (tid < 32) {
        const int j = tid * 4;
        float pv1 = ((s1[j] + s1[j + 1]) + (s1[j + 2] + s1[j + 3])) * (1.0f / 256.0f);
        float pv2 = ((s2[j] + s2[j + 1]) + (s2[j + 2] + s2[j + 3])) * (1.0f / 256.0f);

        float m1  = pv1;
        float m2  = pv2;
        float m11 = pv1 * pv1;
        float m22 = pv2 * pv2;
        float m12 = pv1 * pv2;

#pragma unroll
        for (int off = 16; off > 0; off >>= 1) {
            m1  += __shfl_down_sync(0xffffffffu, m1,  off);
            m2  += __shfl_down_sync(0xffffffffu, m2,  off);
            m11 += __shfl_down_sync(0xffffffffu, m11, off);
            m22 += __shfl_down_sync(0xffffffffu, m22, off);
            m12 += __shfl_down_sync(0xffffffffu, m12, off);
        }

        if (tid == 0) {
            const size_t slab = ((size_t)cb * PHROWS + ph) * 5;
            g_part[slab + 0] = m1;
            g_part[slab + 1] = m2;
            g_part[slab + 2] = m11;
            g_part[slab + 3] = m22;
            g_part[slab + 4] = m12;
        }
    }

    // ---------------- Phase B1: last CTA of this (c,b) group ----------------
    __shared__ bool last1;
    __threadfence();                       // publish this CTA's g_part slot
    if (tid == 0)
        last1 = (atomicAdd(&g_cb_ticket[cb], 1u) == PHROWS - 1);
    __syncthreads();
    if (!last1) return;
    __threadfence();                       // acquire all 32 slabs of (c,b)

    if (tid < 32) {
        // lane = pooled row index within this (c,b) group
        const size_t slab = ((size_t)cb * PHROWS + lane) * 5;
        double m1  = (double)g_part[slab + 0];
        double m2  = (double)g_part[slab + 1];
        double m11 = (double)g_part[slab + 2];
        double m22 = (double)g_part[slab + 3];
        double m12 = (double)g_part[slab + 4];

#pragma unroll
        for (int off = 16; off > 0; off >>= 1) {
            m1  += __shfl_down_sync(0xffffffffu, m1,  off);
            m2  += __shfl_down_sync(0xffffffffu, m2,  off);
            m11 += __shfl_down_sync(0xffffffffu, m11, off);
            m22 += __shfl_down_sync(0xffffffffu, m22, off);
            m12 += __shfl_down_sync(0xffffffffu, m12, off);
        }

        if (lane == 0) {
            const size_t g2 = (size_t)cb * 5;
            g_part2[g2 + 0] = m1;
            g_part2[g2 + 1] = m2;
            g_part2[g2 + 2] = m11;
            g_part2[g2 + 3] = m22;
            g_part2[g2 + 4] = m12;
            g_cb_ticket[cb] = 0u;          // reset for next graph replay
        }
    }

    // ---------------- Phase B2: last (c,b) group of this channel ------------
    __shared__ bool last2;
    __threadfence();                       // publish g_part2 (written by tid 0)
    if (tid == 0)
        last2 = (atomicAdd(&g_chan_ticket[c], 1u) == BATCH - 1);
    __syncthreads();
    if (!last2) return;
    __threadfence();                       // acquire all 8 batch groups of c

    if (tid < 32) {
        // lanes 0..7 hold batch partials; others contribute zero
        double m1 = 0.0, m2 = 0.0, m11 = 0.0, m22 = 0.0, m12 = 0.0;
        if (lane < BATCH) {
            const size_t g2 = ((size_t)lane * CHAN + c) * 5;
            m1  = g_part2[g2 + 0];
            m2  = g_part2[g2 + 1];
            m11 = g_part2[g2 + 2];
            m22 = g_part2[g2 + 3];
            m12 = g_part2[g2 + 4];
        }
#pragma unroll
        for (int off = 4; off > 0; off >>= 1) {
            m1  += __shfl_down_sync(0xffffffffu, m1,  off);
            m2  += __shfl_down_sync(0xffffffffu, m2,  off);
            m11 += __shfl_down_sync(0xffffffffu, m11, off);
            m22 += __shfl_down_sync(0xffffffffu, m22, off);
            m12 += __shfl_down_sync(0xffffffffu, m12, off);
        }

        if (lane == 0) {
            const double n = NPC;
            const double mean1 = m1 / n;
            const double mean2 = m2 / n;
            const double cov = m12 / n - mean1 * mean2;   // biased (torch.mean)
            const double ss1 = m11 - m1 * m1 / n;
            const double ss2 = m22 - m2 * m2 / n;
            const double std1 = sqrt(ss1 / (n - 1.0));    // unbiased (torch.std)
            const double std2 = sqrt(ss2 / (n - 1.0));
            const double corr = cov / (std1 * std2 + 1e-8);
            g_corr[c] = (float)fabs(corr);
            g_chan_ticket[c] = 0u;         // reset for next graph replay
        }
    }

    // ---------------- Phase C: last channel reduces g_corr ------------------
    __shared__ bool last3;
    __threadfence();                       // publish g_corr[c]
    if (tid == 0)
        last3 = (atomicAdd(&g_ticket, 1u) == CHAN - 1);
    __syncthreads();
    if (!last3) return;
    __threadfence();                       // acquire all g_corr writes

    {
        float v = g_corr[tid];
#pragma unroll
        for (int off = 16; off > 0; off >>= 1)
            v += __shfl_down_sync(0xffffffffu, v, off);

        __shared__ float shf[8];
        if (lane == 0) shf[w] = v;
        __syncthreads();

        if (tid == 0) {
            float s = 0.0f;
#pragma unroll
            for (int i = 0; i < 8; i++) s += shf[i];
            out[0] = 1.0f - s * (1.0f / 256.0f);
            g_ticket = 0u;                 // reset for next graph replay
        }
    }
}

extern "C" void kernel_launch(void* const* d_in, const int* in_sizes, int n_in,
                              void* d_out, int out_size) {
    const float* f1 = (const float*)d_in[0];
    const float* f2 = (const float*)d_in[1];
    float* out = (float*)d_out;

    dim3 grid(PHROWS, CHAN, BATCH);   // 32 x 256 x 8 = 65536 CTAs
    fal_fused_kernel<<<grid, 256>>>(f1, f2, out);
}